// round 14
// baseline (speedup 1.0000x reference)
#include <cuda_runtime.h>
#include <cuda_bf16.h>
#include <math.h>
#include <stdint.h>

#define HID      1024
#define BATCH    32
#define NLAYERS  3
#define NOUT     2500
#define NG       50
#define MODES    32
#define GATES    3072
#define ROWS_GRU 6144
#define TILES_GRU (ROWS_GRU/16)     // 384
#define TILES_FC  160               // 2560 rows
#define ROWS_FC  (TILES_FC*16)
#define NS       64                 // k16 steps (K=1024)
#define KSPLIT   4
#define SSEG     (NS/KSPLIT)        // 16 k16-steps per job
#define PSEG     (SSEG*8)           // 128 pair-rows per segment
#define PSTRIDE  40                 // padded u32 stride per pair-row in smem
#define SMEM_SEG (2*PSEG*PSTRIDE*4) // 40960 bytes
#define PF       4                  // weight prefetch depth (k16 steps)

typedef unsigned int u32;

// ---- persistent device scratch ----
// Weight blobs: per (tile, k16-step, lane): {hi uint4, lo uint4} = 32B interleaved
__device__ __align__(256) uint4 g_wg[(size_t)NLAYERS * TILES_GRU * NS * 64];  // 72 MB
__device__ __align__(256) uint4 g_wf[(size_t)TILES_FC * NS * 64];             // 10 MB
// Activation blobs: [512 pairs][hi:32 | lo:32] u32
__device__ u32 g_bx[512 * 64];
__device__ u32 g_bh[NLAYERS][512 * 64];
__device__ float g_P [KSPLIT][ROWS_GRU * BATCH];   // GRU K-split partials
__device__ float g_Pf[KSPLIT][BATCH * ROWS_FC];    // FC partials, TRANSPOSED [ks][b][n]
__device__ float g_hf[NLAYERS][HID * BATCH];       // fp32 h [j][b]
__device__ float g_ct[NG], g_st[NG];

// ---- helpers ----
__device__ __forceinline__ unsigned short f2bf(float v) {
    __nv_bfloat16 h = __float2bfloat16(v);
    return *reinterpret_cast<unsigned short*>(&h);
}
__device__ __forceinline__ float bf2f(unsigned short u) {
    __nv_bfloat16 h = *reinterpret_cast<__nv_bfloat16*>(&u);
    return __bfloat162float(h);
}
__device__ __forceinline__ u32 packbf(float a, float b) {
    return (u32)f2bf(a) | ((u32)f2bf(b) << 16);
}
__device__ __forceinline__ void cp16(void* dst, const void* src) {
    unsigned d = (unsigned)__cvta_generic_to_shared(dst);
    asm volatile("cp.async.cg.shared.global [%0], [%1], 16;\n" :: "r"(d), "l"(src));
}
__device__ __forceinline__ void cp_commit() { asm volatile("cp.async.commit_group;\n"); }
__device__ __forceinline__ void cp_wait0() { asm volatile("cp.async.wait_group 0;\n"); }

#define MMA(c, A, b0, b1)                                                     \
    asm volatile(                                                             \
        "mma.sync.aligned.m16n8k16.row.col.f32.bf16.bf16.f32 "                \
        "{%0,%1,%2,%3}, {%4,%5,%6,%7}, {%8,%9}, {%0,%1,%2,%3};"               \
        : "+f"((c)[0]), "+f"((c)[1]), "+f"((c)[2]), "+f"((c)[3])              \
        : "r"((A).x), "r"((A).y), "r"((A).z), "r"((A).w), "r"(b0), "r"(b1))

// ---- init ----
__global__ void init_kernel(const float* __restrict__ x) {
    int tid = blockIdx.x * blockDim.x + threadIdx.x;
    int stride = gridDim.x * blockDim.x;
    float* h = (float*)g_hf;
    for (int i = tid; i < NLAYERS * HID * BATCH; i += stride) h[i] = 0.0f;
    u32* bh = (u32*)g_bh;
    for (int i = tid; i < NLAYERS * 512 * 64; i += stride) bh[i] = 0u;
    for (int i = tid; i < HID * BATCH; i += stride) {
        int j = i >> 5, b = i & 31;
        float v = x[b * HID + j];
        unsigned short hi = f2bf(v);
        unsigned short lo = f2bf(v - bf2f(hi));
        int p = j >> 1, hf = j & 1;
        ((unsigned short*)g_bx)[(p * 64 + b) * 2 + hf] = hi;
        ((unsigned short*)g_bx)[(p * 64 + 32 + b) * 2 + hf] = lo;
    }
    if (tid < NG) {
        float ang = 6.283185307179586f * (float)tid / (float)NG;
        g_ct[tid] = cosf(ang);
        g_st[tid] = sinf(ang);
    }
}

// ---- prepack: entry = {hi, lo} adjacent (32B per lane per k16-step) ----
__device__ __forceinline__ void pack_frag(uint4* dst, const float* r0p, const float* r1p) {
    float w00 = r0p[0], w01 = r0p[1], w20 = r0p[8], w21 = r0p[9];
    float w10 = r1p[0], w11 = r1p[1], w30 = r1p[8], w31 = r1p[9];
    uint4 hi, lo;
    hi.x = packbf(w00, w01); hi.y = packbf(w10, w11);
    hi.z = packbf(w20, w21); hi.w = packbf(w30, w31);
    lo.x = packbf(w00 - bf2f(f2bf(w00)), w01 - bf2f(f2bf(w01)));
    lo.y = packbf(w10 - bf2f(f2bf(w10)), w11 - bf2f(f2bf(w11)));
    lo.z = packbf(w20 - bf2f(f2bf(w20)), w21 - bf2f(f2bf(w21)));
    lo.w = packbf(w30 - bf2f(f2bf(w30)), w31 - bf2f(f2bf(w31)));
    dst[0] = hi;
    dst[1] = lo;
}

__global__ void prepack_gru_kernel(const float* __restrict__ Wih,
                                   const float* __restrict__ Whh) {
    const int total = NLAYERS * TILES_GRU * NS * 32;
    int stride = gridDim.x * blockDim.x;
    for (int idx = blockIdx.x * blockDim.x + threadIdx.x; idx < total; idx += stride) {
        int lane = idx & 31;
        int s    = (idx >> 5) & (NS - 1);
        int t    = (idx >> 11) % TILES_GRU;
        int l    = (idx >> 11) / TILES_GRU;
        int g = lane >> 2, tig = lane & 3;
        int rA = t * 16 + g, rB = rA + 8;
        int k = s * 16 + 2 * tig;
        const float* WihL = Wih + (size_t)l * GATES * HID;
        const float* WhhL = Whh + (size_t)l * GATES * HID;
        const float* r0p = (rA < GATES) ? WihL + (size_t)rA * HID + k
                                        : WhhL + (size_t)(rA - GATES) * HID + k;
        const float* r1p = (rB < GATES) ? WihL + (size_t)rB * HID + k
                                        : WhhL + (size_t)(rB - GATES) * HID + k;
        pack_frag(g_wg + (((size_t)(l * TILES_GRU + t) * NS + s) * 32 + lane) * 2,
                  r0p, r1p);
    }
}

__global__ void prepack_fc_kernel(const float* __restrict__ fcw) {
    const int total = TILES_FC * NS * 32;
    int stride = gridDim.x * blockDim.x;
    for (int idx = blockIdx.x * blockDim.x + threadIdx.x; idx < total; idx += stride) {
        int lane = idx & 31;
        int s    = (idx >> 5) & (NS - 1);
        int t    = (idx >> 11);
        int g = lane >> 2, tig = lane & 3;
        int rA = t * 16 + g, rB = rA + 8;
        int k = s * 16 + 2 * tig;
        float zbuf[10] = {0,0,0,0,0,0,0,0,0,0};
        const float* r0p = (rA < NOUT) ? fcw + (size_t)rA * HID + k : zbuf;
        const float* r1p = (rB < NOUT) ? fcw + (size_t)rB * HID + k : zbuf;
        pack_frag(g_wf + (((size_t)t * NS + s) * 32 + lane) * 2, r0p, r1p);
    }
}

// ---- stage one K-segment of B into padded smem (256 threads, 2048 cp16) ----
__device__ __forceinline__ void stage_B(u32* Bs, const u32* __restrict__ Bglob,
                                        int ks, int tid) {
    const u32* src = Bglob + (size_t)ks * PSEG * 64;
    #pragma unroll
    for (int it = 0; it < 8; ++it) {
        int i = tid + it * 256;
        int p = i >> 4, seg = i & 15;
        int hl = seg >> 3, ns = seg & 7;
        cp16(Bs + ((hl * PSEG + p) * PSTRIDE) + ns * 4,
             src + p * 64 + hl * 32 + ns * 4);
    }
    cp_commit(); cp_wait0();
}

// ---- per-warp tile x K-segment: SSEG steps, 4 MMA passes, PF-deep prefetch ----
// wq: lane's weight pointer; per-s stride = 64 uint4 (32 lanes * 2 uint4).
__device__ __forceinline__ void gemm_tile(const uint4* __restrict__ wq,
                                          const u32* Bs, int g, int tig,
                                          float acc[4][4]) {
    uint4 ah[PF], al[PF];
    #pragma unroll
    for (int i = 0; i < PF; ++i) { ah[i] = wq[i * 64]; al[i] = wq[i * 64 + 1]; }
    #pragma unroll
    for (int s = 0; s < SSEG; ++s) {
        uint4 cah = ah[s % PF], cal = al[s % PF];
        if (s + PF < SSEG) {
            ah[s % PF] = wq[(s + PF) * 64];
            al[s % PF] = wq[(s + PF) * 64 + 1];
        }
        const int prh = s * 8 + tig;
        #pragma unroll
        for (int nt = 0; nt < 4; ++nt) {
            const int col = g + 8 * nt;
            u32 bh0 = Bs[prh * PSTRIDE + col];
            u32 bh1 = Bs[(prh + 4) * PSTRIDE + col];
            u32 bl0 = Bs[(PSEG + prh) * PSTRIDE + col];
            u32 bl1 = Bs[(PSEG + prh + 4) * PSTRIDE + col];
            MMA(acc[nt], cah, bh0, bh1);
            MMA(acc[nt], cal, bh0, bh1);
            MMA(acc[nt], cah, bl0, bl1);
            MMA(acc[nt], cal, bl0, bl1);
        }
    }
}

// ---- GRU gemm: grid = 48 tile-groups x KSPLIT; block = 256 (8 warps = 8 tiles)
__global__ __launch_bounds__(256) void gemm_gru(
    const uint4* __restrict__ Wblob, const u32* __restrict__ Bx,
    const u32* __restrict__ Bh, float* __restrict__ P)
{
    extern __shared__ u32 Bs[];
    const int tid = threadIdx.x;
    const int warp = tid >> 5, lane = tid & 31;
    const int g = lane >> 2, tig = lane & 3;
    const int tg = blockIdx.x >> 2;          // 0..47
    const int ks = blockIdx.x & 3;
    const int t  = tg * 8 + warp;

    stage_B(Bs, (tg < 24) ? Bx : Bh, ks, tid);
    __syncthreads();

    float acc[4][4] = {};
    gemm_tile(Wblob + (((size_t)t * NS + ks * SSEG) * 32 + lane) * 2, Bs, g, tig, acc);

    float* Pk = P + (size_t)ks * ROWS_GRU * BATCH;
    const int R = t * 16;
    #pragma unroll
    for (int nt = 0; nt < 4; ++nt) {
        int b0 = nt * 8 + 2 * tig;
        *(float2*)(Pk + (size_t)(R + g) * BATCH + b0)     = make_float2(acc[nt][0], acc[nt][1]);
        *(float2*)(Pk + (size_t)(R + g + 8) * BATCH + b0) = make_float2(acc[nt][2], acc[nt][3]);
    }
}

// ---- FC gemm: grid = 20 tile-groups x KSPLIT; Pf TRANSPOSED [ks][b][n] ----
__global__ __launch_bounds__(256) void gemm_fc(
    const uint4* __restrict__ Wblob, const u32* __restrict__ Bh,
    float* __restrict__ P)
{
    extern __shared__ u32 Bs[];
    const int tid = threadIdx.x;
    const int warp = tid >> 5, lane = tid & 31;
    const int g = lane >> 2, tig = lane & 3;
    const int tg = blockIdx.x >> 2;          // 0..19
    const int ks = blockIdx.x & 3;
    const int t  = tg * 8 + warp;

    stage_B(Bs, Bh, ks, tid);
    __syncthreads();

    float acc[4][4] = {};
    gemm_tile(Wblob + (((size_t)t * NS + ks * SSEG) * 32 + lane) * 2, Bs, g, tig, acc);

    float* Pk = P + (size_t)ks * BATCH * ROWS_FC;
    const int rA = t * 16 + g, rB = rA + 8;
    #pragma unroll
    for (int nt = 0; nt < 4; ++nt) {
        int b0 = nt * 8 + 2 * tig;
        Pk[(size_t)b0 * ROWS_FC + rA]       = acc[nt][0];
        Pk[(size_t)(b0 + 1) * ROWS_FC + rA] = acc[nt][1];
        Pk[(size_t)b0 * ROWS_FC + rB]       = acc[nt][2];
        Pk[(size_t)(b0 + 1) * ROWS_FC + rB] = acc[nt][3];
    }
}

// ---- GRU combine: K-reduce partials -> gates -> h (fp32 + blob) ----
__global__ __launch_bounds__(256) void combine_gru_kernel(
    const float* __restrict__ P,
    const float* __restrict__ bih, const float* __restrict__ bhh,
    float* __restrict__ hf, u32* __restrict__ blob)
{
    const int lane = threadIdx.x & 31;
    const int j    = blockIdx.x * 8 + (threadIdx.x >> 5);
    float ir  = bih[j],           iz = bih[HID + j],  inn = bih[2 * HID + j];
    float hr  = bhh[j],           hz = bhh[HID + j],  hn  = bhh[2 * HID + j];
    #pragma unroll
    for (int ks = 0; ks < KSPLIT; ++ks) {
        const float* Pk = P + (size_t)ks * ROWS_GRU * BATCH;
        ir  += Pk[(size_t)(0 * HID + j) * BATCH + lane];
        iz  += Pk[(size_t)(1 * HID + j) * BATCH + lane];
        inn += Pk[(size_t)(2 * HID + j) * BATCH + lane];
        hr  += Pk[(size_t)(GATES + 0 * HID + j) * BATCH + lane];
        hz  += Pk[(size_t)(GATES + 1 * HID + j) * BATCH + lane];
        hn  += Pk[(size_t)(GATES + 2 * HID + j) * BATCH + lane];
    }
    float r = 1.0f / (1.0f + __expf(-(ir + hr)));
    float z = 1.0f / (1.0f + __expf(-(iz + hz)));
    float n = tanhf(inn + r * hn);
    float hp = hf[(size_t)j * BATCH + lane];
    float h = (1.0f - z) * n + z * hp;
    hf[(size_t)j * BATCH + lane] = h;
    unsigned short hi = f2bf(h);
    unsigned short lo = f2bf(h - bf2f(hi));
    int p = j >> 1, half = j & 1;
    ((unsigned short*)blob)[(p * 64 + lane) * 2 + half] = hi;
    ((unsigned short*)blob)[(p * 64 + 32 + lane) * 2 + half] = lo;
}

// ---- spectral crop (fused FC combine): Pf -> out + x blobs ----
__global__ __launch_bounds__(256) void spectral_kernel(
    const float* __restrict__ Pf, const float* __restrict__ fcb,
    float* __restrict__ out)   // [BATCH][NOUT] slice to write
{
    __shared__ float sq[NG * NG];
    __shared__ float Pc[NG][MODES];
    __shared__ float Ps[NG][MODES];
    __shared__ float ct[NG], st[NG];

    const int b = blockIdx.x;
    const int tid = threadIdx.x;

    // fused FC K-reduce + bias; write both out and smem input
    for (int i = tid; i < NOUT; i += 256) {
        float acc = fcb[i];
        #pragma unroll
        for (int ks = 0; ks < KSPLIT; ++ks)
            acc += Pf[(size_t)ks * BATCH * ROWS_FC + (size_t)b * ROWS_FC + i];
        sq[i] = acc;
        out[(size_t)b * NOUT + i] = acc;
    }
    if (tid < NG) { ct[tid] = g_ct[tid]; st[tid] = g_st[tid]; }
    __syncthreads();

    for (int i = tid; i < NG * MODES; i += 256) {
        int n1 = i / MODES, m2 = i % MODES;
        int k2 = (m2 + 34) % NG;
        float sc = 0.f, ss = 0.f;
        int idx = 0;
        #pragma unroll 1
        for (int n2 = 0; n2 < NG; ++n2) {
            float v = sq[n1 * NG + n2];
            sc += v * ct[idx];
            ss += v * st[idx];
            idx += k2; if (idx >= NG) idx -= NG;
        }
        Pc[n1][m2] = sc;
        Ps[n1][m2] = ss;
    }
    __syncthreads();

    for (int i = tid; i < MODES * MODES; i += 256) {
        int m1 = i / MODES, m2 = i % MODES;
        int k1 = (m1 + 34) % NG;
        float acc = 0.f;
        int idx = 0;
        #pragma unroll 1
        for (int n1 = 0; n1 < NG; ++n1) {
            acc += ct[idx] * Pc[n1][m2] - st[idx] * Ps[n1][m2];
            idx += k1; if (idx >= NG) idx -= NG;
        }
        unsigned short hi = f2bf(acc);
        unsigned short lo = f2bf(acc - bf2f(hi));
        int p = i >> 1, half = i & 1;
        ((unsigned short*)g_bx)[(p * 64 + b) * 2 + half] = hi;
        ((unsigned short*)g_bx)[(p * 64 + 32 + b) * 2 + half] = lo;
    }
}

// ---- driver ----
extern "C" void kernel_launch(void* const* d_in, const int* in_sizes, int n_in,
                              void* d_out, int out_size) {
    const float* x   = (const float*)d_in[0];
    const float* Wih = (const float*)d_in[1];
    const float* Whh = (const float*)d_in[2];
    const float* bih = (const float*)d_in[3];
    const float* bhh = (const float*)d_in[4];
    const float* fcw = (const float*)d_in[5];
    const float* fcb = (const float*)d_in[6];
    float* out = (float*)d_out;

    const int T = out_size / (BATCH * NOUT);

    uint4* wg; cudaGetSymbolAddress((void**)&wg, g_wg);
    uint4* wf; cudaGetSymbolAddress((void**)&wf, g_wf);
    u32* bx;   cudaGetSymbolAddress((void**)&bx, g_bx);
    u32* bh;   cudaGetSymbolAddress((void**)&bh, g_bh);
    float* P;  cudaGetSymbolAddress((void**)&P, g_P);
    float* Pf; cudaGetSymbolAddress((void**)&Pf, g_Pf);
    float* hf; cudaGetSymbolAddress((void**)&hf, g_hf);

    init_kernel<<<148, 256>>>(x);
    prepack_gru_kernel<<<2048, 256>>>(Wih, Whh);
    prepack_fc_kernel<<<1280, 256>>>(fcw);

    for (int t = 0; t < T; ++t) {
        const u32* inp = bx;
        for (int l = 0; l < NLAYERS; ++l) {
            u32* bhl = bh + (size_t)l * 512 * 64;
            gemm_gru<<<48 * KSPLIT, 256, SMEM_SEG>>>(
                wg + (size_t)l * TILES_GRU * NS * 64, inp, bhl, P);
            combine_gru_kernel<<<HID / 8, 256>>>(P, bih + l * GATES, bhh + l * GATES,
                                                 hf + (size_t)l * HID * BATCH, bhl);
            inp = bhl;
        }
        float* oslice = out + (size_t)t * BATCH * NOUT;
        gemm_fc<<<20 * KSPLIT, 256, SMEM_SEG>>>(
            wf, bh + (size_t)(NLAYERS - 1) * 512 * 64, Pf);
        spectral_kernel<<<BATCH, 256>>>(Pf, fcb, oslice);
    }
}

// round 16
// speedup vs baseline: 1.5046x; 1.5046x over previous
#include <cuda_runtime.h>
#include <cuda_bf16.h>
#include <math.h>
#include <stdint.h>

#define HID      1024
#define BATCH    32
#define NLAYERS  3
#define NOUT     2500
#define NG       50
#define MODES    32
#define GATES    3072
#define ROWS_GRU 6144
#define TILES_GRU (ROWS_GRU/16)     // 384
#define TILES_FC  160               // 2560 rows
#define ROWS_FC  (TILES_FC*16)
#define NS       64                 // k16 steps (K=1024)
#define KSPLIT   4
#define SSEG     (NS/KSPLIT)        // 16 k16-steps per job
#define PSEG     (SSEG*8)           // 128 pair-rows per segment
#define PSTRIDE  40                 // padded u32 stride per pair-row in smem
#define SMEM_SEG (2*PSEG*PSTRIDE*4) // 40960 bytes
#define PF       4                  // weight prefetch depth (k16 steps)

typedef unsigned int u32;

// ---- persistent device scratch ----
// Weight blobs (R9 layout): per (tile,s): 64 uint4 = [hi: lanes 0..31][lo: lanes 0..31]
__device__ __align__(16) uint4 g_wg[(size_t)NLAYERS * TILES_GRU * NS * 64];  // 72 MB
__device__ __align__(16) uint4 g_wf[(size_t)TILES_FC * NS * 64];             // 10 MB
// Activation blobs: [512 pairs][hi:32 | lo:32] u32
__device__ u32 g_bx[512 * 64];
__device__ u32 g_bh[NLAYERS][512 * 64];
__device__ float g_P [KSPLIT][ROWS_GRU * BATCH];   // GRU K-split partials
__device__ float g_Pf[KSPLIT][BATCH * ROWS_FC];    // FC partials, TRANSPOSED [ks][b][n]
__device__ float g_hf[NLAYERS][HID * BATCH];       // fp32 h [j][b]
__device__ float g_ct[NG], g_st[NG];

// ---- helpers ----
__device__ __forceinline__ unsigned short f2bf(float v) {
    __nv_bfloat16 h = __float2bfloat16(v);
    return *reinterpret_cast<unsigned short*>(&h);
}
__device__ __forceinline__ float bf2f(unsigned short u) {
    __nv_bfloat16 h = *reinterpret_cast<__nv_bfloat16*>(&u);
    return __bfloat162float(h);
}
__device__ __forceinline__ u32 packbf(float a, float b) {
    return (u32)f2bf(a) | ((u32)f2bf(b) << 16);
}
__device__ __forceinline__ void cp16(void* dst, const void* src) {
    unsigned d = (unsigned)__cvta_generic_to_shared(dst);
    asm volatile("cp.async.cg.shared.global [%0], [%1], 16;\n" :: "r"(d), "l"(src));
}
__device__ __forceinline__ void cp_commit() { asm volatile("cp.async.commit_group;\n"); }
__device__ __forceinline__ void cp_wait0() { asm volatile("cp.async.wait_group 0;\n"); }

#define MMA(c, A, b0, b1)                                                     \
    asm volatile(                                                             \
        "mma.sync.aligned.m16n8k16.row.col.f32.bf16.bf16.f32 "                \
        "{%0,%1,%2,%3}, {%4,%5,%6,%7}, {%8,%9}, {%0,%1,%2,%3};"               \
        : "+f"((c)[0]), "+f"((c)[1]), "+f"((c)[2]), "+f"((c)[3])              \
        : "r"((A).x), "r"((A).y), "r"((A).z), "r"((A).w), "r"(b0), "r"(b1))

// ---- init ----
__global__ void init_kernel(const float* __restrict__ x) {
    int tid = blockIdx.x * blockDim.x + threadIdx.x;
    int stride = gridDim.x * blockDim.x;
    float* h = (float*)g_hf;
    for (int i = tid; i < NLAYERS * HID * BATCH; i += stride) h[i] = 0.0f;
    u32* bh = (u32*)g_bh;
    for (int i = tid; i < NLAYERS * 512 * 64; i += stride) bh[i] = 0u;
    for (int i = tid; i < HID * BATCH; i += stride) {
        int j = i >> 5, b = i & 31;
        float v = x[b * HID + j];
        unsigned short hi = f2bf(v);
        unsigned short lo = f2bf(v - bf2f(hi));
        int p = j >> 1, hf = j & 1;
        ((unsigned short*)g_bx)[(p * 64 + b) * 2 + hf] = hi;
        ((unsigned short*)g_bx)[(p * 64 + 32 + b) * 2 + hf] = lo;
    }
    if (tid < NG) {
        float ang = 6.283185307179586f * (float)tid / (float)NG;
        g_ct[tid] = cosf(ang);
        g_st[tid] = sinf(ang);
    }
}

// ---- prepack (R9 layout: dst[0]=hi, dst[32]=lo) ----
__device__ __forceinline__ void pack_frag(uint4* dst_hi, const float* r0p, const float* r1p) {
    float w00 = r0p[0], w01 = r0p[1], w20 = r0p[8], w21 = r0p[9];
    float w10 = r1p[0], w11 = r1p[1], w30 = r1p[8], w31 = r1p[9];
    uint4 hi, lo;
    hi.x = packbf(w00, w01); hi.y = packbf(w10, w11);
    hi.z = packbf(w20, w21); hi.w = packbf(w30, w31);
    lo.x = packbf(w00 - bf2f(f2bf(w00)), w01 - bf2f(f2bf(w01)));
    lo.y = packbf(w10 - bf2f(f2bf(w10)), w11 - bf2f(f2bf(w11)));
    lo.z = packbf(w20 - bf2f(f2bf(w20)), w21 - bf2f(f2bf(w21)));
    lo.w = packbf(w30 - bf2f(f2bf(w30)), w31 - bf2f(f2bf(w31)));
    dst_hi[0]  = hi;
    dst_hi[32] = lo;
}

__global__ void prepack_gru_kernel(const float* __restrict__ Wih,
                                   const float* __restrict__ Whh) {
    const int total = NLAYERS * TILES_GRU * NS * 32;
    int stride = gridDim.x * blockDim.x;
    for (int idx = blockIdx.x * blockDim.x + threadIdx.x; idx < total; idx += stride) {
        int lane = idx & 31;
        int s    = (idx >> 5) & (NS - 1);
        int t    = (idx >> 11) % TILES_GRU;
        int l    = (idx >> 11) / TILES_GRU;
        int g = lane >> 2, tig = lane & 3;
        int rA = t * 16 + g, rB = rA + 8;
        int k = s * 16 + 2 * tig;
        const float* WihL = Wih + (size_t)l * GATES * HID;
        const float* WhhL = Whh + (size_t)l * GATES * HID;
        const float* r0p = (rA < GATES) ? WihL + (size_t)rA * HID + k
                                        : WhhL + (size_t)(rA - GATES) * HID + k;
        const float* r1p = (rB < GATES) ? WihL + (size_t)rB * HID + k
                                        : WhhL + (size_t)(rB - GATES) * HID + k;
        pack_frag(g_wg + ((size_t)(l * TILES_GRU + t) * NS + s) * 64 + lane, r0p, r1p);
    }
}

__global__ void prepack_fc_kernel(const float* __restrict__ fcw) {
    const int total = TILES_FC * NS * 32;
    int stride = gridDim.x * blockDim.x;
    for (int idx = blockIdx.x * blockDim.x + threadIdx.x; idx < total; idx += stride) {
        int lane = idx & 31;
        int s    = (idx >> 5) & (NS - 1);
        int t    = (idx >> 11);
        int g = lane >> 2, tig = lane & 3;
        int rA = t * 16 + g, rB = rA + 8;
        int k = s * 16 + 2 * tig;
        float zbuf[10] = {0,0,0,0,0,0,0,0,0,0};
        const float* r0p = (rA < NOUT) ? fcw + (size_t)rA * HID + k : zbuf;
        const float* r1p = (rB < NOUT) ? fcw + (size_t)rB * HID + k : zbuf;
        pack_frag(g_wf + ((size_t)t * NS + s) * 64 + lane, r0p, r1p);
    }
}

// ---- stage one K-segment of B into padded smem (256 threads, 2048 cp16) ----
__device__ __forceinline__ void stage_B(u32* Bs, const u32* __restrict__ Bglob,
                                        int ks, int tid) {
    const u32* src = Bglob + (size_t)ks * PSEG * 64;
    #pragma unroll
    for (int it = 0; it < 8; ++it) {
        int i = tid + it * 256;
        int p = i >> 4, seg = i & 15;
        int hl = seg >> 3, ns = seg & 7;
        cp16(Bs + ((hl * PSEG + p) * PSTRIDE) + ns * 4,
             src + p * 64 + hl * 32 + ns * 4);
    }
    cp_commit(); cp_wait0();
}

// ---- per-warp tile x K-segment: SSEG steps, 4 MMA passes, PF-deep prefetch ----
__device__ __forceinline__ void gemm_tile(const uint4* __restrict__ wq,
                                          const u32* Bs, int g, int tig,
                                          float acc[4][4]) {
    uint4 ah[PF], al[PF];
    #pragma unroll
    for (int i = 0; i < PF; ++i) { ah[i] = wq[i * 64]; al[i] = wq[i * 64 + 32]; }
    #pragma unroll
    for (int s = 0; s < SSEG; ++s) {
        uint4 cah = ah[s % PF], cal = al[s % PF];
        if (s + PF < SSEG) {
            ah[s % PF] = wq[(s + PF) * 64];
            al[s % PF] = wq[(s + PF) * 64 + 32];
        }
        const int prh = s * 8 + tig;
        #pragma unroll
        for (int nt = 0; nt < 4; ++nt) {
            const int col = g + 8 * nt;
            u32 bh0 = Bs[prh * PSTRIDE + col];
            u32 bh1 = Bs[(prh + 4) * PSTRIDE + col];
            u32 bl0 = Bs[(PSEG + prh) * PSTRIDE + col];
            u32 bl1 = Bs[(PSEG + prh + 4) * PSTRIDE + col];
            MMA(acc[nt], cah, bh0, bh1);
            MMA(acc[nt], cal, bh0, bh1);
            MMA(acc[nt], cah, bl0, bl1);
            MMA(acc[nt], cal, bl0, bl1);
        }
    }
}

// ---- GRU gemm: grid = 48 tile-groups x KSPLIT; block = 256 (8 warps = 8 tiles)
__global__ __launch_bounds__(256) void gemm_gru(
    const uint4* __restrict__ Wblob, const u32* __restrict__ Bx,
    const u32* __restrict__ Bh, float* __restrict__ P)
{
    extern __shared__ u32 Bs[];
    const int tid = threadIdx.x;
    const int warp = tid >> 5, lane = tid & 31;
    const int g = lane >> 2, tig = lane & 3;
    const int tg = blockIdx.x >> 2;          // 0..47
    const int ks = blockIdx.x & 3;
    const int t  = tg * 8 + warp;

    stage_B(Bs, (tg < 24) ? Bx : Bh, ks, tid);
    __syncthreads();

    float acc[4][4] = {};
    gemm_tile(Wblob + ((size_t)t * NS + ks * SSEG) * 64 + lane, Bs, g, tig, acc);

    float* Pk = P + (size_t)ks * ROWS_GRU * BATCH;
    const int R = t * 16;
    #pragma unroll
    for (int nt = 0; nt < 4; ++nt) {
        int b0 = nt * 8 + 2 * tig;
        *(float2*)(Pk + (size_t)(R + g) * BATCH + b0)     = make_float2(acc[nt][0], acc[nt][1]);
        *(float2*)(Pk + (size_t)(R + g + 8) * BATCH + b0) = make_float2(acc[nt][2], acc[nt][3]);
    }
}

// ---- FC gemm: grid = 20 tile-groups x KSPLIT; Pf TRANSPOSED [ks][b][n] ----
__global__ __launch_bounds__(256) void gemm_fc(
    const uint4* __restrict__ Wblob, const u32* __restrict__ Bh,
    float* __restrict__ P)
{
    extern __shared__ u32 Bs[];
    const int tid = threadIdx.x;
    const int warp = tid >> 5, lane = tid & 31;
    const int g = lane >> 2, tig = lane & 3;
    const int tg = blockIdx.x >> 2;          // 0..19
    const int ks = blockIdx.x & 3;
    const int t  = tg * 8 + warp;

    stage_B(Bs, Bh, ks, tid);
    __syncthreads();

    float acc[4][4] = {};
    gemm_tile(Wblob + ((size_t)t * NS + ks * SSEG) * 64 + lane, Bs, g, tig, acc);

    float* Pk = P + (size_t)ks * BATCH * ROWS_FC;
    const int rA = t * 16 + g, rB = rA + 8;
    #pragma unroll
    for (int nt = 0; nt < 4; ++nt) {
        int b0 = nt * 8 + 2 * tig;
        Pk[(size_t)b0 * ROWS_FC + rA]       = acc[nt][0];
        Pk[(size_t)(b0 + 1) * ROWS_FC + rA] = acc[nt][1];
        Pk[(size_t)b0 * ROWS_FC + rB]       = acc[nt][2];
        Pk[(size_t)(b0 + 1) * ROWS_FC + rB] = acc[nt][3];
    }
}

// ---- GRU combine: K-reduce partials -> gates -> h (fp32 + blob) ----
__global__ __launch_bounds__(256) void combine_gru_kernel(
    const float* __restrict__ P,
    const float* __restrict__ bih, const float* __restrict__ bhh,
    float* __restrict__ hf, u32* __restrict__ blob)
{
    const int lane = threadIdx.x & 31;
    const int j    = blockIdx.x * 8 + (threadIdx.x >> 5);
    float ir  = bih[j],           iz = bih[HID + j],  inn = bih[2 * HID + j];
    float hr  = bhh[j],           hz = bhh[HID + j],  hn  = bhh[2 * HID + j];
    #pragma unroll
    for (int ks = 0; ks < KSPLIT; ++ks) {
        const float* Pk = P + (size_t)ks * ROWS_GRU * BATCH;
        ir  += Pk[(size_t)(0 * HID + j) * BATCH + lane];
        iz  += Pk[(size_t)(1 * HID + j) * BATCH + lane];
        inn += Pk[(size_t)(2 * HID + j) * BATCH + lane];
        hr  += Pk[(size_t)(GATES + 0 * HID + j) * BATCH + lane];
        hz  += Pk[(size_t)(GATES + 1 * HID + j) * BATCH + lane];
        hn  += Pk[(size_t)(GATES + 2 * HID + j) * BATCH + lane];
    }
    float r = 1.0f / (1.0f + __expf(-(ir + hr)));
    float z = 1.0f / (1.0f + __expf(-(iz + hz)));
    float n = tanhf(inn + r * hn);
    float hp = hf[(size_t)j * BATCH + lane];
    float h = (1.0f - z) * n + z * hp;
    hf[(size_t)j * BATCH + lane] = h;
    unsigned short hi = f2bf(h);
    unsigned short lo = f2bf(h - bf2f(hi));
    int p = j >> 1, half = j & 1;
    ((unsigned short*)blob)[(p * 64 + lane) * 2 + half] = hi;
    ((unsigned short*)blob)[(p * 64 + 32 + lane) * 2 + half] = lo;
}

// ---- spectral crop (fused FC combine): Pf -> out + x blobs ----
__global__ __launch_bounds__(256) void spectral_kernel(
    const float* __restrict__ Pf, const float* __restrict__ fcb,
    float* __restrict__ out)   // [BATCH][NOUT] slice to write
{
    __shared__ float sq[NG * NG];
    __shared__ float Pc[NG][MODES];
    __shared__ float Ps[NG][MODES];
    __shared__ float ct[NG], st[NG];

    const int b = blockIdx.x;
    const int tid = threadIdx.x;

    // fused FC K-reduce + bias; write both out and smem input
    for (int i = tid; i < NOUT; i += 256) {
        float acc = fcb[i];
        #pragma unroll
        for (int ks = 0; ks < KSPLIT; ++ks)
            acc += Pf[(size_t)ks * BATCH * ROWS_FC + (size_t)b * ROWS_FC + i];
        sq[i] = acc;
        out[(size_t)b * NOUT + i] = acc;
    }
    if (tid < NG) { ct[tid] = g_ct[tid]; st[tid] = g_st[tid]; }
    __syncthreads();

    for (int i = tid; i < NG * MODES; i += 256) {
        int n1 = i / MODES, m2 = i % MODES;
        int k2 = (m2 + 34) % NG;
        float sc = 0.f, ss = 0.f;
        int idx = 0;
        #pragma unroll 1
        for (int n2 = 0; n2 < NG; ++n2) {
            float v = sq[n1 * NG + n2];
            sc += v * ct[idx];
            ss += v * st[idx];
            idx += k2; if (idx >= NG) idx -= NG;
        }
        Pc[n1][m2] = sc;
        Ps[n1][m2] = ss;
    }
    __syncthreads();

    for (int i = tid; i < MODES * MODES; i += 256) {
        int m1 = i / MODES, m2 = i % MODES;
        int k1 = (m1 + 34) % NG;
        float acc = 0.f;
        int idx = 0;
        #pragma unroll 1
        for (int n1 = 0; n1 < NG; ++n1) {
            acc += ct[idx] * Pc[n1][m2] - st[idx] * Ps[n1][m2];
            idx += k1; if (idx >= NG) idx -= NG;
        }
        unsigned short hi = f2bf(acc);
        unsigned short lo = f2bf(acc - bf2f(hi));
        int p = i >> 1, half = i & 1;
        ((unsigned short*)g_bx)[(p * 64 + b) * 2 + half] = hi;
        ((unsigned short*)g_bx)[(p * 64 + 32 + b) * 2 + half] = lo;
    }
}

// ---- driver ----
extern "C" void kernel_launch(void* const* d_in, const int* in_sizes, int n_in,
                              void* d_out, int out_size) {
    const float* x   = (const float*)d_in[0];
    const float* Wih = (const float*)d_in[1];
    const float* Whh = (const float*)d_in[2];
    const float* bih = (const float*)d_in[3];
    const float* bhh = (const float*)d_in[4];
    const float* fcw = (const float*)d_in[5];
    const float* fcb = (const float*)d_in[6];
    float* out = (float*)d_out;

    const int T = out_size / (BATCH * NOUT);

    uint4* wg; cudaGetSymbolAddress((void**)&wg, g_wg);
    uint4* wf; cudaGetSymbolAddress((void**)&wf, g_wf);
    u32* bx;   cudaGetSymbolAddress((void**)&bx, g_bx);
    u32* bh;   cudaGetSymbolAddress((void**)&bh, g_bh);
    float* P;  cudaGetSymbolAddress((void**)&P, g_P);
    float* Pf; cudaGetSymbolAddress((void**)&Pf, g_Pf);
    float* hf; cudaGetSymbolAddress((void**)&hf, g_hf);

    init_kernel<<<148, 256>>>(x);
    prepack_gru_kernel<<<2048, 256>>>(Wih, Whh);
    prepack_fc_kernel<<<1280, 256>>>(fcw);

    for (int t = 0; t < T; ++t) {
        const u32* inp = bx;
        for (int l = 0; l < NLAYERS; ++l) {
            u32* bhl = bh + (size_t)l * 512 * 64;
            gemm_gru<<<48 * KSPLIT, 256, SMEM_SEG>>>(
                wg + (size_t)l * TILES_GRU * NS * 64, inp, bhl, P);
            combine_gru_kernel<<<HID / 8, 256>>>(P, bih + l * GATES, bhh + l * GATES,
                                                 hf + (size_t)l * HID * BATCH, bhl);
            inp = bhl;
        }
        float* oslice = out + (size_t)t * BATCH * NOUT;
        gemm_fc<<<20 * KSPLIT, 256, SMEM_SEG>>>(
            wf, bh + (size_t)(NLAYERS - 1) * 512 * 64, Pf);
        spectral_kernel<<<BATCH, 256>>>(Pf, fcb, oslice);
    }
}